// round 13
// baseline (speedup 1.0000x reference)
#include <cuda_runtime.h>

// Problem constants (fixed by the dataset)
#define BB   64
#define NN   2048
#define EE   32768
#define DD   256
#define HH   256

#define SE      4                  // edge-pass blocks per batch
#define EPB     (EE / SE)          // 8192 edges per block
#define SPLIT_M 16                 // gather blocks per batch
#define MPB     (NN / SPLIT_M)     // 128 rows per gather block

#define CNB     128                // chain kernel grid (1 block/SM, co-resident)

// Scratch (__device__ globals, allocation-free; device-side refs only).
__device__ float g_wp[SE * BB * NN];
__device__ float g_up[SE * BB * NN];
__device__ float g_cp[SE * BB];
__device__ float g_s0p[SPLIT_M * BB * DD];
__device__ float g_T[HH * HH];      // T  = W2 @ fc1w
__device__ float g_M[HH * HH];      // M  = (W1 @ T) * invL
__device__ float g_vb[HH];          // vb = (b1 @ T) * invL
__device__ float g_k0[HH];          // k0 = b2 @ fc1w + fc1b

// Grid-barrier state (R11/R12-proven; invariants hold across graph replays).
__device__ int g2_cnt[2];
__device__ int g2_flag[2];

__device__ __forceinline__ void gbar2(int i) {
    __syncthreads();
    if (threadIdx.x == 0) {
        __threadfence();
        volatile int* vf = (volatile int*)&g2_flag[i];
        int sense = *vf;
        int prev = atomicAdd(&g2_cnt[i], 1);
        if (prev == CNB - 1) {
            g2_cnt[i] = 0;
            __threadfence();
            atomicExch(&g2_flag[i], sense ^ 1);
        } else {
            while (*vf == sense) __nanosleep(64);
        }
        __threadfence();
    }
    __syncthreads();
}

// ---------------------------------------------------------------------------
// Kernel 1: w partials.  grid (BB, SE)=256, 512 threads.  (unchanged)
// ---------------------------------------------------------------------------
__global__ __launch_bounds__(512) void k_w(const int* __restrict__ adj_row,
                                           const int* __restrict__ adj_col,
                                           const float* __restrict__ adj_val,
                                           const int* __restrict__ curlen) {
    __shared__ float sw[NN];
    __shared__ float sc;
    int b   = blockIdx.x;
    int se  = blockIdx.y;
    int tid = threadIdx.x;

    for (int i = tid; i < NN; i += 512) sw[i] = 0.f;
    if (tid == 0) sc = 0.f;
    __syncthreads();

    int L = curlen ? *curlen : 512;
    size_t base = (size_t)b * EE + (size_t)se * EPB;
    const int4*   r4 = (const int4*)  (adj_row + base);
    const int4*   c4 = (const int4*)  (adj_col + base);
    const float4* v4 = (const float4*)(adj_val + base);
    const int NV = EPB / 4;

    float cpart = 0.f;
    for (int i = tid; i < NV; i += 512) {
        int4 r = r4[i]; int4 c = c4[i]; float4 v = v4[i];
        if (r.x < L) { atomicAdd(&sw[c.x], v.x); cpart += v.x; }
        if (r.y < L) { atomicAdd(&sw[c.y], v.y); cpart += v.y; }
        if (r.z < L) { atomicAdd(&sw[c.z], v.z); cpart += v.z; }
        if (r.w < L) { atomicAdd(&sw[c.w], v.w); cpart += v.w; }
    }
    #pragma unroll
    for (int off = 16; off > 0; off >>= 1)
        cpart += __shfl_down_sync(0xFFFFFFFFu, cpart, off);
    if ((tid & 31) == 0) atomicAdd(&sc, cpart);
    __syncthreads();

    float* dst = g_wp + ((size_t)se * BB + b) * NN;
    for (int i = tid; i < NN; i += 512) dst[i] = sw[i];
    if (tid == 0) g_cp[se * BB + b] = sc;
}

// ---------------------------------------------------------------------------
// Kernel 2: u partials.  grid (BB, SE)=256, 512 threads.  (unchanged)
// ---------------------------------------------------------------------------
__global__ __launch_bounds__(512) void k_u(const int* __restrict__ adj_row,
                                           const int* __restrict__ adj_col,
                                           const float* __restrict__ adj_val) {
    __shared__ float sw[NN];
    __shared__ float su[NN];
    int b   = blockIdx.x;
    int se  = blockIdx.y;
    int tid = threadIdx.x;

    for (int i = tid; i < NN; i += 512) {
        float w = 0.f;
        #pragma unroll
        for (int s = 0; s < SE; s++)
            w += g_wp[((size_t)s * BB + b) * NN + i];
        sw[i] = w;
        su[i] = 0.f;
    }
    __syncthreads();

    size_t base = (size_t)b * EE + (size_t)se * EPB;
    const int4*   r4 = (const int4*)  (adj_row + base);
    const int4*   c4 = (const int4*)  (adj_col + base);
    const float4* v4 = (const float4*)(adj_val + base);
    const int NV = EPB / 4;

    for (int i = tid; i < NV; i += 512) {
        int4 r = r4[i]; int4 c = c4[i]; float4 v = v4[i];
        atomicAdd(&su[c.x], v.x * sw[r.x]);
        atomicAdd(&su[c.y], v.y * sw[r.y]);
        atomicAdd(&su[c.z], v.z * sw[r.z]);
        atomicAdd(&su[c.w], v.w * sw[r.w]);
    }
    __syncthreads();

    float* dst = g_up + ((size_t)se * BB + b) * NN;
    for (int i = tid; i < NN; i += 512) dst[i] = su[i];
}

// ---------------------------------------------------------------------------
// Kernel 3: S0 partials. grid (BB, SPLIT_M)=1024, 512 threads. (unchanged)
// ---------------------------------------------------------------------------
__global__ __launch_bounds__(512) void k_s0(const int* __restrict__ neighbors,
                                            const float* __restrict__ emb) {
    __shared__ float  su[MPB];
    __shared__ int    snb[MPB];
    __shared__ float4 red[8][64];
    int b   = blockIdx.x;
    int tid = threadIdx.x;
    int m0  = blockIdx.y * MPB;

    if (tid < MPB) {
        float u = 0.f;
        #pragma unroll
        for (int s = 0; s < SE; s++)
            u += g_up[((size_t)s * BB + b) * NN + m0 + tid];
        su[tid]  = u;
        snb[tid] = neighbors[(size_t)b * NN + m0 + tid];
    }
    __syncthreads();

    int dg = tid & 63;
    int rg = tid >> 6;

    float4 acc = make_float4(0.f, 0.f, 0.f, 0.f);
    #pragma unroll
    for (int i = rg; i < MPB; i += 8) {
        float u = su[i];
        const float4* row = (const float4*)(emb + (size_t)snb[i] * DD);
        float4 e = __ldg(&row[dg]);
        acc.x += u * e.x;
        acc.y += u * e.y;
        acc.z += u * e.z;
        acc.w += u * e.w;
    }
    red[rg][dg] = acc;
    __syncthreads();

    if (tid < 64) {
        float4 s = make_float4(0.f, 0.f, 0.f, 0.f);
        #pragma unroll
        for (int r = 0; r < 8; r++) {
            float4 a = red[r][tid];
            s.x += a.x; s.y += a.y; s.z += a.z; s.w += a.w;
        }
        float4* dst = (float4*)(g_s0p + ((size_t)blockIdx.y * BB + b) * DD);
        dst[tid] = s;
    }
}

// ---------------------------------------------------------------------------
// Kernel 4: collapsed chain. out = relu(S0 @ M + c*vb + k0) with
//   T = W2@fc1w, M = (W1@T)*invL, vb = (b1@T)*invL, k0 = b2@fc1w + fc1b.
// grid 128, 1024 threads, 3 phases separated by gbar2:
//   Phase T / Phase M: weight GEMM, 8x64 output tile per block (32x4 tiling),
//     thread = (kh = tid>>9 K-half, r = (tid>>6)&7, c = tid&63), coalesced.
//   Phase OUT: blocks < 32, (bg = bid>>1: 4 batches, half = bid&1: 128 cols),
//     single GEMV round with K-half split; S0 partial-reduce folded in.
// ---------------------------------------------------------------------------
__global__ __launch_bounds__(1024, 1) void k_chainW(
        const float* __restrict__ W1,   const float* __restrict__ b1,
        const float* __restrict__ W2,   const float* __restrict__ b2,
        const float* __restrict__ fc1w, const float* __restrict__ fc1b,
        const int* __restrict__ curlen,
        float* __restrict__ out) {
    __shared__ float sW[8][256];
    __shared__ float sred[8][64];
    __shared__ float sredv[2][8][64];
    __shared__ float sS[4][260];
    __shared__ float sred2[4][128];
    __shared__ float scv[4];

    int bid  = blockIdx.x;
    int tid  = threadIdx.x;
    int rowt = bid >> 2;        // 0..31 -> 8 rows
    int colt = bid & 3;         // 0..3  -> 64 cols
    int kh   = tid >> 9;        // 0..1
    int r    = (tid >> 6) & 7;  // 0..7
    int c    = tid & 63;        // 0..63
    int col  = colt * 64 + c;
    int L    = curlen ? __ldg(curlen) : 512;
    float invL = 1.f / (float)L;

    // ================= Phase T: g_T = W2 @ fc1w =================
    #pragma unroll
    for (int k = 0; k < 2; k++) {
        int i = tid + k * 1024;
        sW[i >> 8][i & 255] = __ldg(&W2[(size_t)(rowt * 8 + (i >> 8)) * HH + (i & 255)]);
    }
    __syncthreads();
    {
        float acc = 0.f;
        int j0 = kh * 128;
        #pragma unroll 8
        for (int j = 0; j < 128; j++)
            acc += sW[r][j0 + j] * __ldg(&fc1w[(size_t)(j0 + j) * HH + col]);
        if (kh) sred[r][c] = acc;
        __syncthreads();
        if (!kh) {
            acc += sred[r][c];
            g_T[(size_t)(rowt * 8 + r) * HH + col] = acc;
        }
    }
    gbar2(0);

    // ================= Phase M: g_M = (W1 @ T)*invL; vb, k0 =================
    #pragma unroll
    for (int k = 0; k < 2; k++) {
        int i = tid + k * 1024;
        sW[i >> 8][i & 255] = __ldg(&W1[(size_t)(rowt * 8 + (i >> 8)) * HH + (i & 255)]);
    }
    __syncthreads();
    {
        float acc = 0.f;
        int j0 = kh * 128;
        #pragma unroll 8
        for (int j = 0; j < 128; j++)
            acc += sW[r][j0 + j] * g_T[(size_t)(j0 + j) * HH + col];
        if (kh) sred[r][c] = acc;
        __syncthreads();
        if (!kh) {
            acc += sred[r][c];
            g_M[(size_t)(rowt * 8 + r) * HH + col] = acc * invL;
        }
    }
    // vb/k0 on blocks 0..3 (64 cols each)
    if (bid < 4) {
        int c2 = tid & 63, wh = (tid >> 6) & 1, ks = tid >> 7;  // ks 0..7
        int col2 = bid * 64 + c2;
        float a = 0.f;
        if (wh == 0) {
            #pragma unroll 8
            for (int k = 0; k < 32; k++) {
                int kk = ks * 32 + k;
                a += __ldg(&b1[kk]) * g_T[(size_t)kk * HH + col2];
            }
        } else {
            #pragma unroll 8
            for (int k = 0; k < 32; k++) {
                int kk = ks * 32 + k;
                a += __ldg(&b2[kk]) * __ldg(&fc1w[(size_t)kk * HH + col2]);
            }
        }
        sredv[wh][ks][c2] = a;
    }
    __syncthreads();
    if (bid < 4 && tid < 128) {
        int wh = tid >> 6, c2 = tid & 63;
        float s = 0.f;
        #pragma unroll
        for (int k = 0; k < 8; k++) s += sredv[wh][k][c2];
        if (wh == 0) g_vb[bid * 64 + c2] = s * invL;
        else         g_k0[bid * 64 + c2] = s + __ldg(&fc1b[bid * 64 + c2]);
    }
    gbar2(1);

    // ================= Phase OUT: out = relu(S0 @ M + c*vb + k0) ============
    if (bid < 32) {
        int bg = bid >> 1, half = bid & 1;
        int b0 = bg * 4;
        {
            int bb = tid >> 8, hh = tid & 255;
            float s0 = 0.f;
            #pragma unroll
            for (int sm = 0; sm < SPLIT_M; sm++)
                s0 += __ldg(&g_s0p[((size_t)sm * BB + b0 + bb) * DD + hh]);
            sS[bb][hh] = s0;
            if (tid < 4) {
                float cc = 0.f;
                #pragma unroll
                for (int s = 0; s < SE; s++) cc += g_cp[s * BB + b0 + tid];
                scv[tid] = cc;
            }
        }
        __syncthreads();

        int kh2 = tid >> 9, bb2 = (tid >> 7) & 3, c3 = tid & 127;
        int col3 = half * 128 + c3;
        float acc = 0.f;
        int k0i = kh2 * 128;
        #pragma unroll 8
        for (int k = 0; k < 128; k++)
            acc += sS[bb2][k0i + k] * g_M[(size_t)(k0i + k) * HH + col3];
        if (kh2) sred2[bb2][c3] = acc;
        __syncthreads();
        if (!kh2) {
            acc += sred2[bb2][c3];
            float y = acc + scv[bb2] * g_vb[col3] + g_k0[col3];
            y = y > 0.f ? y : 0.f;
            out[(size_t)(b0 + bb2) * HH + col3] = y;
        }
    }
}

// ---------------------------------------------------------------------------
extern "C" void kernel_launch(void* const* d_in, const int* in_sizes, int n_in,
                              void* d_out, int out_size) {
    const int*   neighbors = (const int*)  d_in[0];
    const int*   adj_row   = (const int*)  d_in[1];
    const int*   adj_col   = (const int*)  d_in[2];
    const float* adj_val   = (const float*)d_in[3];
    const float* emb       = (const float*)d_in[4];
    const float* W1        = (const float*)d_in[5];
    const float* b1        = (const float*)d_in[6];
    const float* W2        = (const float*)d_in[7];
    const float* b2        = (const float*)d_in[8];
    const float* fc1w      = (const float*)d_in[9];
    const float* fc1b      = (const float*)d_in[10];
    const int*   curlen    = (n_in >= 12) ? (const int*)d_in[11] : nullptr;
    float*       out       = (float*)d_out;

    k_w     <<<dim3(BB, SE), 512>>>(adj_row, adj_col, adj_val, curlen);
    k_u     <<<dim3(BB, SE), 512>>>(adj_row, adj_col, adj_val);
    k_s0    <<<dim3(BB, SPLIT_M), 512>>>(neighbors, emb);
    k_chainW<<<CNB, 1024>>>(W1, b1, W2, b2, fc1w, fc1b, curlen, out);
}

// round 14
// speedup vs baseline: 1.0223x; 1.0223x over previous
#include <cuda_runtime.h>

// Problem constants (fixed by the dataset)
#define BB   64
#define NN   2048
#define EE   32768
#define DD   256
#define HH   256

#define SE      4                  // edge-split per batch
#define EPB     (EE / SE)          // 8192 edges per split
#define SPLIT_M 16                 // gather blocks per batch
#define MPB     (NN / SPLIT_M)     // 128 rows per gather block

#define WNB     256                // k_wu grid (co-resident: 4 blk/SM x 148 = 592)
#define CNB     128                // chain grid (1 block/SM)

// Scratch (__device__ globals, allocation-free; device-side refs only).
__device__ float g_wp[SE * BB * NN];         // w partials
__device__ float g_u[BB * NN];               // u (REDG-accumulated)
__device__ float g_cp[SE * BB];              // c partials
__device__ float g_s0p[SPLIT_M * BB * DD];   // S0 partials
__device__ float g_v1[BB * HH];
__device__ float g_v2[BB * HH];

// Grid-barrier state (proven pattern; invariants hold across graph replays:
// cnt returns to 0, flag toggles, sense read strictly pre-flip).
__device__ int gw_cnt, gw_flag;              // k_wu barrier (256 blocks)
__device__ int g2_cnt[2], g2_flag[2];        // chain barriers (128 blocks)

__device__ __forceinline__ void gbar_w() {
    __syncthreads();
    if (threadIdx.x == 0) {
        __threadfence();
        volatile int* vf = (volatile int*)&gw_flag;
        int sense = *vf;
        int prev = atomicAdd(&gw_cnt, 1);
        if (prev == WNB - 1) {
            gw_cnt = 0;
            __threadfence();
            atomicExch(&gw_flag, sense ^ 1);
        } else {
            while (*vf == sense) __nanosleep(64);
        }
        __threadfence();
    }
    __syncthreads();
}

__device__ __forceinline__ void gbar2(int i) {
    __syncthreads();
    if (threadIdx.x == 0) {
        __threadfence();
        volatile int* vf = (volatile int*)&g2_flag[i];
        int sense = *vf;
        int prev = atomicAdd(&g2_cnt[i], 1);
        if (prev == CNB - 1) {
            g2_cnt[i] = 0;
            __threadfence();
            atomicExch(&g2_flag[i], sense ^ 1);
        } else {
            while (*vf == sense) __nanosleep(64);
        }
        __threadfence();
    }
    __syncthreads();
}

// ---------------------------------------------------------------------------
// Kernel 1 (fused edge passes): grid WNB=256 (item = (b, se)), 512 threads.
//  pre:    zero g_u (one element per thread: 256*512 = 131072 = BB*NN)
//  pass 1: w partials into smem -> g_wp, c -> g_cp
//  gbar_w  (co-resident 256 blocks)
//  pass 2: stage full w (sum SE partials) in smem; per edge
//          REDG g_u[b*NN+col] += val * w[row]   (no-return global atomic:
//          1.29 cyc/lane spread vs 2 for shared ATOMS; no zero/writeout)
// ---------------------------------------------------------------------------
__global__ __launch_bounds__(512, 1) void k_wu(const int* __restrict__ adj_row,
                                               const int* __restrict__ adj_col,
                                               const float* __restrict__ adj_val,
                                               const int* __restrict__ curlen) {
    __shared__ float sw[NN];
    __shared__ float sc;
    int bid = blockIdx.x;
    int b   = bid >> 2;
    int se  = bid & 3;
    int tid = threadIdx.x;

    // zero g_u slice (exactly one element per thread chip-wide)
    g_u[bid * 512 + tid] = 0.f;

    for (int i = tid; i < NN; i += 512) sw[i] = 0.f;
    if (tid == 0) sc = 0.f;
    __syncthreads();

    int L = curlen ? __ldg(curlen) : 512;
    size_t base = (size_t)b * EE + (size_t)se * EPB;
    const int4*   r4 = (const int4*)  (adj_row + base);
    const int4*   c4 = (const int4*)  (adj_col + base);
    const float4* v4 = (const float4*)(adj_val + base);
    const int NV = EPB / 4;  // 2048

    // ---- pass 1: w scatter + c reduce ----
    float cpart = 0.f;
    for (int i = tid; i < NV; i += 512) {
        int4 r = r4[i]; int4 c = c4[i]; float4 v = v4[i];
        if (r.x < L) { atomicAdd(&sw[c.x], v.x); cpart += v.x; }
        if (r.y < L) { atomicAdd(&sw[c.y], v.y); cpart += v.y; }
        if (r.z < L) { atomicAdd(&sw[c.z], v.z); cpart += v.z; }
        if (r.w < L) { atomicAdd(&sw[c.w], v.w); cpart += v.w; }
    }
    #pragma unroll
    for (int off = 16; off > 0; off >>= 1)
        cpart += __shfl_down_sync(0xFFFFFFFFu, cpart, off);
    if ((tid & 31) == 0) atomicAdd(&sc, cpart);
    __syncthreads();

    {
        float* dst = g_wp + ((size_t)se * BB + b) * NN;
        for (int i = tid; i < NN; i += 512) dst[i] = sw[i];
        if (tid == 0) g_cp[se * BB + b] = sc;
    }

    gbar_w();

    // ---- pass 2: stage full w, REDG-scatter u to global ----
    for (int i = tid; i < NN; i += 512) {
        float w = 0.f;
        #pragma unroll
        for (int s = 0; s < SE; s++)
            w += g_wp[((size_t)s * BB + b) * NN + i];
        sw[i] = w;
    }
    __syncthreads();

    float* ub = g_u + (size_t)b * NN;
    for (int i = tid; i < NV; i += 512) {
        int4 r = r4[i]; int4 c = c4[i]; float4 v = v4[i];
        atomicAdd(&ub[c.x], v.x * sw[r.x]);
        atomicAdd(&ub[c.y], v.y * sw[r.y]);
        atomicAdd(&ub[c.z], v.z * sw[r.z]);
        atomicAdd(&ub[c.w], v.w * sw[r.w]);
    }
}

// ---------------------------------------------------------------------------
// Kernel 2: S0 partials. grid (BB, SPLIT_M)=1024, 512 threads.
// (same as R12 except u staging is a single g_u load)
// ---------------------------------------------------------------------------
__global__ __launch_bounds__(512) void k_s0(const int* __restrict__ neighbors,
                                            const float* __restrict__ emb) {
    __shared__ float  su[MPB];
    __shared__ int    snb[MPB];
    __shared__ float4 red[8][64];
    int b   = blockIdx.x;
    int tid = threadIdx.x;
    int m0  = blockIdx.y * MPB;

    if (tid < MPB) {
        su[tid]  = g_u[(size_t)b * NN + m0 + tid];
        snb[tid] = neighbors[(size_t)b * NN + m0 + tid];
    }
    __syncthreads();

    int dg = tid & 63;
    int rg = tid >> 6;

    float4 acc = make_float4(0.f, 0.f, 0.f, 0.f);
    #pragma unroll
    for (int i = rg; i < MPB; i += 8) {
        float u = su[i];
        const float4* row = (const float4*)(emb + (size_t)snb[i] * DD);
        float4 e = __ldg(&row[dg]);
        acc.x += u * e.x;
        acc.y += u * e.y;
        acc.z += u * e.z;
        acc.w += u * e.w;
    }
    red[rg][dg] = acc;
    __syncthreads();

    if (tid < 64) {
        float4 s = make_float4(0.f, 0.f, 0.f, 0.f);
        #pragma unroll
        for (int r = 0; r < 8; r++) {
            float4 a = red[r][tid];
            s.x += a.x; s.y += a.y; s.z += a.z; s.w += a.w;
        }
        float4* dst = (float4*)(g_s0p + ((size_t)blockIdx.y * BB + b) * DD);
        dst[tid] = s;
    }
}

// ---------------------------------------------------------------------------
// Kernel 3: persistent chain (R12, unchanged). grid CNB=128, 1024 threads.
// ---------------------------------------------------------------------------
__global__ __launch_bounds__(1024, 1) void k_chainp(
        const float* __restrict__ W1,   const float* __restrict__ b1,
        const float* __restrict__ W2,   const float* __restrict__ b2,
        const float* __restrict__ fc1w, const float* __restrict__ fc1b,
        const int* __restrict__ curlen,
        float* __restrict__ out) {
    __shared__ float sA[4][260];
    __shared__ float sred[32][32][4];
    __shared__ float scv[4];
    int bid = blockIdx.x;
    int tid = threadIdx.x;
    int bg  = bid >> 3;
    int cg  = bid & 7;
    int b0  = bg * 4;
    int h   = tid & 31;
    int ks  = tid >> 5;
    int col = cg * 32 + h;
    int L = curlen ? __ldg(curlen) : 512;
    float invL = 1.f / (float)L;

    // ---- stage 1 A: reduce S0 partials; c partials ----
    {
        int bb = tid >> 8;
        int hh = tid & 255;
        float s0 = 0.f;
        #pragma unroll
        for (int sm = 0; sm < SPLIT_M; sm++)
            s0 += __ldg(&g_s0p[((size_t)sm * BB + b0 + bb) * DD + hh]);
        sA[bb][hh] = s0;
        if (tid < 4) {
            float c = 0.f;
            #pragma unroll
            for (int s = 0; s < SE; s++) c += g_cp[s * BB + b0 + tid];
            scv[tid] = c;
        }
    }
    __syncthreads();

    // ---- stage 1: v1 = S0 @ W1 + c*b1 ----
    {
        float a0 = 0.f, a1 = 0.f, a2 = 0.f, a3 = 0.f;
        #pragma unroll
        for (int j = 0; j < 8; j++) {
            int k = ks * 8 + j;
            float w = __ldg(&W1[(size_t)k * HH + col]);
            a0 += sA[0][k] * w; a1 += sA[1][k] * w;
            a2 += sA[2][k] * w; a3 += sA[3][k] * w;
        }
        sred[ks][h][0] = a0; sred[ks][h][1] = a1;
        sred[ks][h][2] = a2; sred[ks][h][3] = a3;
        __syncthreads();
        if (tid < 128) {
            int bb = tid >> 5, hh = tid & 31;
            float s = 0.f;
            #pragma unroll
            for (int k2 = 0; k2 < 32; k2++) s += sred[k2][hh][bb];
            s += scv[bb] * __ldg(&b1[cg * 32 + hh]);
            g_v1[(size_t)(b0 + bb) * HH + cg * 32 + hh] = s;
        }
    }
    gbar2(0);

    // ---- stage 2 A ----
    {
        int bb = tid >> 8, hh = tid & 255;
        sA[bb][hh] = g_v1[(size_t)(b0 + bb) * HH + hh];
    }
    __syncthreads();

    // ---- stage 2: v2 = (v1 @ W2)*invL + b2 ----
    {
        float a0 = 0.f, a1 = 0.f, a2 = 0.f, a3 = 0.f;
        #pragma unroll
        for (int j = 0; j < 8; j++) {
            int k = ks * 8 + j;
            float w = __ldg(&W2[(size_t)k * HH + col]);
            a0 += sA[0][k] * w; a1 += sA[1][k] * w;
            a2 += sA[2][k] * w; a3 += sA[3][k] * w;
        }
        sred[ks][h][0] = a0; sred[ks][h][1] = a1;
        sred[ks][h][2] = a2; sred[ks][h][3] = a3;
        __syncthreads();
        if (tid < 128) {
            int bb = tid >> 5, hh = tid & 31;
            float s = 0.f;
            #pragma unroll
            for (int k2 = 0; k2 < 32; k2++) s += sred[k2][hh][bb];
            s = s * invL + __ldg(&b2[cg * 32 + hh]);
            g_v2[(size_t)(b0 + bb) * HH + cg * 32 + hh] = s;
        }
    }
    gbar2(1);

    // ---- stage 3 A ----
    {
        int bb = tid >> 8, hh = tid & 255;
        sA[bb][hh] = g_v2[(size_t)(b0 + bb) * HH + hh];
    }
    __syncthreads();

    // ---- stage 3: out = relu(v2 @ fc1w + fc1b) ----
    {
        float a0 = 0.f, a1 = 0.f, a2 = 0.f, a3 = 0.f;
        #pragma unroll
        for (int j = 0; j < 8; j++) {
            int k = ks * 8 + j;
            float w = __ldg(&fc1w[(size_t)k * HH + col]);
            a0 += sA[0][k] * w; a1 += sA[1][k] * w;
            a2 += sA[2][k] * w; a3 += sA[3][k] * w;
        }
        sred[ks][h][0] = a0; sred[ks][h][1] = a1;
        sred[ks][h][2] = a2; sred[ks][h][3] = a3;
        __syncthreads();
        if (tid < 128) {
            int bb = tid >> 5, hh = tid & 31;
            float s = 0.f;
            #pragma unroll
            for (int k2 = 0; k2 < 32; k2++) s += sred[k2][hh][bb];
            s += __ldg(&fc1b[cg * 32 + hh]);
            s = s > 0.f ? s : 0.f;
            out[(size_t)(b0 + bb) * HH + cg * 32 + hh] = s;
        }
    }
}

// ---------------------------------------------------------------------------
extern "C" void kernel_launch(void* const* d_in, const int* in_sizes, int n_in,
                              void* d_out, int out_size) {
    const int*   neighbors = (const int*)  d_in[0];
    const int*   adj_row   = (const int*)  d_in[1];
    const int*   adj_col   = (const int*)  d_in[2];
    const float* adj_val   = (const float*)d_in[3];
    const float* emb       = (const float*)d_in[4];
    const float* W1        = (const float*)d_in[5];
    const float* b1        = (const float*)d_in[6];
    const float* W2        = (const float*)d_in[7];
    const float* b2        = (const float*)d_in[8];
    const float* fc1w      = (const float*)d_in[9];
    const float* fc1b      = (const float*)d_in[10];
    const int*   curlen    = (n_in >= 12) ? (const int*)d_in[11] : nullptr;
    float*       out       = (float*)d_out;

    k_wu    <<<WNB, 512>>>(adj_row, adj_col, adj_val, curlen);
    k_s0    <<<dim3(BB, SPLIT_M), 512>>>(neighbors, emb);
    k_chainp<<<CNB, 1024>>>(W1, b1, W2, b2, fc1w, fc1b, curlen, out);
}

// round 15
// speedup vs baseline: 1.4187x; 1.3878x over previous
#include <cuda_runtime.h>

// Problem constants (fixed by the dataset)
#define BB   64
#define NN   2048
#define EE   32768
#define DD   256
#define HH   256

#define SE      4                  // edge-pass blocks per batch
#define EPB     (EE / SE)          // 8192 edges per block
#define SPLIT_M 16                 // gather blocks per batch
#define MPB     (NN / SPLIT_M)     // 128 rows per gather block

#define CNB     128                // chain kernel grid (1 block/SM, co-resident)

// Scratch (__device__ globals, allocation-free; device-side refs only).
__device__ float g_wp[SE * BB * NN];
__device__ float g_up[SE * BB * NN];
__device__ float g_cp[SE * BB];
__device__ float g_s0p[SPLIT_M * BB * DD];
__device__ float g_v1[BB * HH];
__device__ float g_v2[BB * HH];

// Tree grid-barrier state (replay-safe: leaves/root self-reset to 0, flag
// toggles, sense read strictly pre-arrival). 8 leaves x 16 blocks, root of 8.
__device__ int g2_leaf[2][8];
__device__ int g2_root[2];
__device__ int g2_flag[2];

__device__ __forceinline__ void gbar2(int i) {
    __syncthreads();
    if (threadIdx.x == 0) {
        __threadfence();
        volatile int* vf = (volatile int*)&g2_flag[i];
        int sense = *vf;
        int leaf = blockIdx.x & 7;
        int p = atomicAdd(&g2_leaf[i][leaf], 1);
        if (p == 15) {
            g2_leaf[i][leaf] = 0;           // safe: untouched until next launch
            int q = atomicAdd(&g2_root[i], 1);
            if (q == 7) {
                g2_root[i] = 0;
                __threadfence();
                atomicExch(&g2_flag[i], sense ^ 1);
            } else {
                while (*vf == sense) __nanosleep(32);
            }
        } else {
            while (*vf == sense) __nanosleep(32);
        }
        __threadfence();
    }
    __syncthreads();
}

// ---------------------------------------------------------------------------
// Kernel 1: w partials.  grid (BB, SE)=256, 512 threads.  (R12, unchanged)
// ---------------------------------------------------------------------------
__global__ __launch_bounds__(512) void k_w(const int* __restrict__ adj_row,
                                           const int* __restrict__ adj_col,
                                           const float* __restrict__ adj_val,
                                           const int* __restrict__ curlen) {
    __shared__ float sw[NN];
    __shared__ float sc;
    int b   = blockIdx.x;
    int se  = blockIdx.y;
    int tid = threadIdx.x;

    for (int i = tid; i < NN; i += 512) sw[i] = 0.f;
    if (tid == 0) sc = 0.f;
    __syncthreads();

    int L = curlen ? *curlen : 512;
    size_t base = (size_t)b * EE + (size_t)se * EPB;
    const int4*   r4 = (const int4*)  (adj_row + base);
    const int4*   c4 = (const int4*)  (adj_col + base);
    const float4* v4 = (const float4*)(adj_val + base);
    const int NV = EPB / 4;

    float cpart = 0.f;
    for (int i = tid; i < NV; i += 512) {
        int4 r = r4[i]; int4 c = c4[i]; float4 v = v4[i];
        if (r.x < L) { atomicAdd(&sw[c.x], v.x); cpart += v.x; }
        if (r.y < L) { atomicAdd(&sw[c.y], v.y); cpart += v.y; }
        if (r.z < L) { atomicAdd(&sw[c.z], v.z); cpart += v.z; }
        if (r.w < L) { atomicAdd(&sw[c.w], v.w); cpart += v.w; }
    }
    #pragma unroll
    for (int off = 16; off > 0; off >>= 1)
        cpart += __shfl_down_sync(0xFFFFFFFFu, cpart, off);
    if ((tid & 31) == 0) atomicAdd(&sc, cpart);
    __syncthreads();

    float* dst = g_wp + ((size_t)se * BB + b) * NN;
    for (int i = tid; i < NN; i += 512) dst[i] = sw[i];
    if (tid == 0) g_cp[se * BB + b] = sc;
}

// ---------------------------------------------------------------------------
// Kernel 2: u partials.  grid (BB, SE)=256, 512 threads.  (R12, unchanged)
// ---------------------------------------------------------------------------
__global__ __launch_bounds__(512) void k_u(const int* __restrict__ adj_row,
                                           const int* __restrict__ adj_col,
                                           const float* __restrict__ adj_val) {
    __shared__ float sw[NN];
    __shared__ float su[NN];
    int b   = blockIdx.x;
    int se  = blockIdx.y;
    int tid = threadIdx.x;

    for (int i = tid; i < NN; i += 512) {
        float w = 0.f;
        #pragma unroll
        for (int s = 0; s < SE; s++)
            w += g_wp[((size_t)s * BB + b) * NN + i];
        sw[i] = w;
        su[i] = 0.f;
    }
    __syncthreads();

    size_t base = (size_t)b * EE + (size_t)se * EPB;
    const int4*   r4 = (const int4*)  (adj_row + base);
    const int4*   c4 = (const int4*)  (adj_col + base);
    const float4* v4 = (const float4*)(adj_val + base);
    const int NV = EPB / 4;

    for (int i = tid; i < NV; i += 512) {
        int4 r = r4[i]; int4 c = c4[i]; float4 v = v4[i];
        atomicAdd(&su[c.x], v.x * sw[r.x]);
        atomicAdd(&su[c.y], v.y * sw[r.y]);
        atomicAdd(&su[c.z], v.z * sw[r.z]);
        atomicAdd(&su[c.w], v.w * sw[r.w]);
    }
    __syncthreads();

    float* dst = g_up + ((size_t)se * BB + b) * NN;
    for (int i = tid; i < NN; i += 512) dst[i] = su[i];
}

// ---------------------------------------------------------------------------
// Kernel 3: S0 partials. grid (BB, SPLIT_M)=1024, 512 threads. (unchanged)
// ---------------------------------------------------------------------------
__global__ __launch_bounds__(512) void k_s0(const int* __restrict__ neighbors,
                                            const float* __restrict__ emb) {
    __shared__ float  su[MPB];
    __shared__ int    snb[MPB];
    __shared__ float4 red[8][64];
    int b   = blockIdx.x;
    int tid = threadIdx.x;
    int m0  = blockIdx.y * MPB;

    if (tid < MPB) {
        float u = 0.f;
        #pragma unroll
        for (int s = 0; s < SE; s++)
            u += g_up[((size_t)s * BB + b) * NN + m0 + tid];
        su[tid]  = u;
        snb[tid] = neighbors[(size_t)b * NN + m0 + tid];
    }
    __syncthreads();

    int dg = tid & 63;
    int rg = tid >> 6;

    float4 acc = make_float4(0.f, 0.f, 0.f, 0.f);
    #pragma unroll
    for (int i = rg; i < MPB; i += 8) {
        float u = su[i];
        const float4* row = (const float4*)(emb + (size_t)snb[i] * DD);
        float4 e = __ldg(&row[dg]);
        acc.x += u * e.x;
        acc.y += u * e.y;
        acc.z += u * e.z;
        acc.w += u * e.w;
    }
    red[rg][dg] = acc;
    __syncthreads();

    if (tid < 64) {
        float4 s = make_float4(0.f, 0.f, 0.f, 0.f);
        #pragma unroll
        for (int r = 0; r < 8; r++) {
            float4 a = red[r][tid];
            s.x += a.x; s.y += a.y; s.z += a.z; s.w += a.w;
        }
        float4* dst = (float4*)(g_s0p + ((size_t)blockIdx.y * BB + b) * DD);
        dst[tid] = s;
    }
}

// ---------------------------------------------------------------------------
// Kernel 4: persistent chain (R12 layout; tree barrier + conflict-free sred).
// grid CNB=128, 1024 threads. Block = 4 batches (bg=bid>>3) x 32 cols
// (cg=bid&7). sred dims [bb][ks][h]: writer lanes (consec h) and reader lanes
// (consec h) both hit consecutive banks -> no 4-way conflicts.
// ---------------------------------------------------------------------------
__global__ __launch_bounds__(1024, 1) void k_chainp(
        const float* __restrict__ W1,   const float* __restrict__ b1,
        const float* __restrict__ W2,   const float* __restrict__ b2,
        const float* __restrict__ fc1w, const float* __restrict__ fc1b,
        const int* __restrict__ curlen,
        float* __restrict__ out) {
    __shared__ float sA[4][260];
    __shared__ float sred[4][32][32];     // [bb][ks][h]
    __shared__ float scv[4];
    int bid = blockIdx.x;
    int tid = threadIdx.x;
    int bg  = bid >> 3;
    int cg  = bid & 7;
    int b0  = bg * 4;
    int h   = tid & 31;
    int ks  = tid >> 5;
    int col = cg * 32 + h;
    int L = curlen ? __ldg(curlen) : 512;
    float invL = 1.f / (float)L;

    // ---- stage 1 A: reduce S0 partials; c partials ----
    {
        int bb = tid >> 8;
        int hh = tid & 255;
        float s0 = 0.f;
        #pragma unroll
        for (int sm = 0; sm < SPLIT_M; sm++)
            s0 += __ldg(&g_s0p[((size_t)sm * BB + b0 + bb) * DD + hh]);
        sA[bb][hh] = s0;
        if (tid < 4) {
            float c = 0.f;
            #pragma unroll
            for (int s = 0; s < SE; s++) c += g_cp[s * BB + b0 + tid];
            scv[tid] = c;
        }
    }
    __syncthreads();

    // ---- stage 1: v1 = S0 @ W1 + c*b1 ----
    {
        float a0 = 0.f, a1 = 0.f, a2 = 0.f, a3 = 0.f;
        #pragma unroll
        for (int j = 0; j < 8; j++) {
            int k = ks * 8 + j;
            float w = __ldg(&W1[(size_t)k * HH + col]);
            a0 += sA[0][k] * w; a1 += sA[1][k] * w;
            a2 += sA[2][k] * w; a3 += sA[3][k] * w;
        }
        sred[0][ks][h] = a0; sred[1][ks][h] = a1;
        sred[2][ks][h] = a2; sred[3][ks][h] = a3;
        __syncthreads();
        if (tid < 128) {
            int bb = tid >> 5, hh = tid & 31;
            float s = 0.f;
            #pragma unroll
            for (int k2 = 0; k2 < 32; k2++) s += sred[bb][k2][hh];
            s += scv[bb] * __ldg(&b1[cg * 32 + hh]);
            g_v1[(size_t)(b0 + bb) * HH + cg * 32 + hh] = s;
        }
    }
    gbar2(0);

    // ---- stage 2 A ----
    {
        int bb = tid >> 8, hh = tid & 255;
        sA[bb][hh] = g_v1[(size_t)(b0 + bb) * HH + hh];
    }
    __syncthreads();

    // ---- stage 2: v2 = (v1 @ W2)*invL + b2 ----
    {
        float a0 = 0.f, a1 = 0.f, a2 = 0.f, a3 = 0.f;
        #pragma unroll
        for (int j = 0; j < 8; j++) {
            int k = ks * 8 + j;
            float w = __ldg(&W2[(size_t)k * HH + col]);
            a0 += sA[0][k] * w; a1 += sA[1][k] * w;
            a2 += sA[2][k] * w; a3 += sA[3][k] * w;
        }
        sred[0][ks][h] = a0; sred[1][ks][h] = a1;
        sred[2][ks][h] = a2; sred[3][ks][h] = a3;
        __syncthreads();
        if (tid < 128) {
            int bb = tid >> 5, hh = tid & 31;
            float s = 0.f;
            #pragma unroll
            for (int k2 = 0; k2 < 32; k2++) s += sred[bb][k2][hh];
            s = s * invL + __ldg(&b2[cg * 32 + hh]);
            g_v2[(size_t)(b0 + bb) * HH + cg * 32 + hh] = s;
        }
    }
    gbar2(1);

    // ---- stage 3 A ----
    {
        int bb = tid >> 8, hh = tid & 255;
        sA[bb][hh] = g_v2[(size_t)(b0 + bb) * HH + hh];
    }
    __syncthreads();

    // ---- stage 3: out = relu(v2 @ fc1w + fc1b) ----
    {
        float a0 = 0.f, a1 = 0.f, a2 = 0.f, a3 = 0.f;
        #pragma unroll
        for (int j = 0; j < 8; j++) {
            int k = ks * 8 + j;
            float w = __ldg(&fc1w[(size_t)k * HH + col]);
            a0 += sA[0][k] * w; a1 += sA[1][k] * w;
            a2 += sA[2][k] * w; a3 += sA[3][k] * w;
        }
        sred[0][ks][h] = a0; sred[1][ks][h] = a1;
        sred[2][ks][h] = a2; sred[3][ks][h] = a3;
        __syncthreads();
        if (tid < 128) {
            int bb = tid >> 5, hh = tid & 31;
            float s = 0.f;
            #pragma unroll
            for (int k2 = 0; k2 < 32; k2++) s += sred[bb][k2][hh];
            s += __ldg(&fc1b[cg * 32 + hh]);
            s = s > 0.f ? s : 0.f;
            out[(size_t)(b0 + bb) * HH + cg * 32 + hh] = s;
        }
    }
}

// ---------------------------------------------------------------------------
extern "C" void kernel_launch(void* const* d_in, const int* in_sizes, int n_in,
                              void* d_out, int out_size) {
    const int*   neighbors = (const int*)  d_in[0];
    const int*   adj_row   = (const int*)  d_in[1];
    const int*   adj_col   = (const int*)  d_in[2];
    const float* adj_val   = (const float*)d_in[3];
    const float* emb       = (const float*)d_in[4];
    const float* W1        = (const float*)d_in[5];
    const float* b1        = (const float*)d_in[6];
    const float* W2        = (const float*)d_in[7];
    const float* b2        = (const float*)d_in[8];
    const float* fc1w      = (const float*)d_in[9];
    const float* fc1b      = (const float*)d_in[10];
    const int*   curlen    = (n_in >= 12) ? (const int*)d_in[11] : nullptr;
    float*       out       = (float*)d_out;

    k_w     <<<dim3(BB, SE), 512>>>(adj_row, adj_col, adj_val, curlen);
    k_u     <<<dim3(BB, SE), 512>>>(adj_row, adj_col, adj_val);
    k_s0    <<<dim3(BB, SPLIT_M), 512>>>(neighbors, emb);
    k_chainp<<<CNB, 1024>>>(W1, b1, W2, b2, fc1w, fc1b, curlen, out);
}